// round 12
// baseline (speedup 1.0000x reference)
#include <cuda_runtime.h>
#include <cuda_fp16.h>
#include <cstdint>
#include <math.h>

#define H 256
#define BM 64
#define NSEG 512
#define AS 528           // A row stride in bytes (264 fp16, padded)

typedef unsigned long long u64;
typedef unsigned int       u32;

// -------- device scratch (no allocations allowed) --------
__device__ int g_is64;
// W (fp16) packed per-lane, LDG.128-friendly:
// u32 index = ((gemm*16 + ks)*4 + wc)*512 + lane*16 + ntl*2 + reg
__device__ __align__(16) u32 g_Wb[65536];

// -------- SMEM layout (bytes) --------
#define OFF_AHI   0                    // [64][264] fp16 = 33792
#define OFF_BSEG  67584                // 64 ints (gtile fp32 uses 0..67583)
#define OFF_BIAS  67840                // b1[256], b2[256] fp32 = 2048
#define SMEM_TOTAL 69888
// g tile (final): fp32 [64][264] overlays bytes 0..67583 (A dead by then)

// -------- PTX helpers (legal on plain sm_103 target) --------
__device__ __forceinline__ void ldm4(u32* r, u32 addr) {
    asm volatile("ldmatrix.sync.aligned.m8n8.x4.shared.b16 {%0,%1,%2,%3},[%4];"
        : "=r"(r[0]), "=r"(r[1]), "=r"(r[2]), "=r"(r[3]) : "r"(addr));
}
__device__ __forceinline__ void mma16816(float* d, const u32* a, const u32* b) {
    asm volatile(
        "mma.sync.aligned.m16n8k16.row.col.f32.f16.f16.f32 "
        "{%0,%1,%2,%3},{%4,%5,%6,%7},{%8,%9},{%0,%1,%2,%3};"
        : "+f"(d[0]), "+f"(d[1]), "+f"(d[2]), "+f"(d[3])
        : "r"(a[0]), "r"(a[1]), "r"(a[2]), "r"(a[3]), "r"(b[0]), "r"(b[1]));
}

// ---------------------------------------------------------------------------
// Kernel 1: W prep (fp32 -> fp16, LDG.128 fragment layout) + zero out +
// batch dtype detection. 512 blocks x 256 threads.
// ---------------------------------------------------------------------------
__global__ void prep_kernel(const float* __restrict__ W1,
                            const float* __restrict__ W2,
                            float* out,
                            const void* batch, int N) {
    int id = blockIdx.x * 256 + threadIdx.x;     // 131072 total
    // zero output (262144 floats)
    out[id] = 0.0f;
    out[id + 131072] = 0.0f;
    if (id == 0) {
        const int* bw = (const int*)batch;
        int o = ((N - 1) & 1) ? (N - 1) : (N - 2);
        int orv = 0;
        if (o >= 4) orv = bw[o] | bw[o - 2] | bw[o - 4];
        else if (o >= 0) orv = bw[o];
        g_is64 = (orv == 0) ? 1 : 0;
    }
    // W pack
    int gemm = id >> 16, rem = id & 65535;
    int n = rem >> 8, k = rem & 255;
    float w = (gemm ? W2 : W1)[n * H + k];
    __half hi = __float2half_rn(w);
    int ks = k >> 4, kk = k & 15;
    int nt = n >> 3, nn = n & 7;
    int wc = nt >> 3, ntl = nt & 7;
    int lane = nn * 4 + ((kk & 7) >> 1);
    int reg  = kk >> 3;
    int half_i = kk & 1;
    u32 base = (u32)(((gemm * 16 + ks) * 4 + wc) * 512 + lane * 16 + ntl * 2 + reg);
    __half* wb = (__half*)g_Wb;
    wb[(size_t)base * 2 + half_i] = hi;
}

// ---------------------------------------------------------------------------
// Kernel 2: fused  relu(xW1^T+b1) -> sigmoid(hW2^T+b2) gate -> segment reduce.
// Plain fp16 HMMA, warp grid 2x4. B fragments: 4 x LDG.128 per k16-step per
// warp (contiguous per-lane pack), double-buffered. No counts work here.
// ---------------------------------------------------------------------------
extern "C" __global__ void __launch_bounds__(256, 2)
fused_kernel(const float* __restrict__ x, const void* __restrict__ batch,
             const float* __restrict__ b1, const float* __restrict__ b2,
             float* __restrict__ out, int N)
{
    extern __shared__ char smem[];
    const u32 sb = (u32)__cvta_generic_to_shared(smem);
    const int tid  = threadIdx.x;
    const int w    = tid >> 5;
    const int lane = tid & 31;
    const int wr   = w >> 2;            // 0..1: row group (32 rows)
    const int wc   = w & 3;             // 0..3: col group (64 cols)
    const int row0 = blockIdx.x * BM;
    float* sb1 = (float*)(smem + OFF_BIAS);
    float* sb2 = sb1 + H;
    int* bseg = (int*)(smem + OFF_BSEG);

    // ---- bias + segment ids ----
    sb1[tid] = b1[tid];
    sb2[tid] = b2[tid];
    if (tid < BM) {
        int r = row0 + tid;
        int s = -1;
        if (r < N) {
            if (g_is64) s = (int)((const long long*)batch)[r];
            else        s = ((const int*)batch)[r];
        }
        bseg[tid] = s;
    }

    // ---- load x tile fp32 -> fp16 into AHI ([64][264] padded) ----
    {
        const float4* xg = (const float4*)x;
        #pragma unroll
        for (int it = 0; it < 16; ++it) {
            int f = tid + it * 256;            // 4096 float4s
            int r = f >> 6, k4 = f & 63;
            float4 v = make_float4(0.f, 0.f, 0.f, 0.f);
            if (row0 + r < N) v = xg[(size_t)(row0 + r) * (H / 4) + k4];
            __half2 h01 = __floats2half2_rn(v.x, v.y);
            __half2 h23 = __floats2half2_rn(v.z, v.w);
            char* pa = smem + OFF_AHI + r * AS + k4 * 8;
            *(__half2*)pa = h01;  *(__half2*)(pa + 4) = h23;
        }
    }
    __syncthreads();   // x tile visible to all warps

    float acc[2][8][4];
    #pragma unroll
    for (int i = 0; i < 2; ++i)
        #pragma unroll
        for (int j = 0; j < 8; ++j)
            #pragma unroll
            for (int q = 0; q < 4; ++q) acc[i][j][q] = 0.f;

    // ---- 2 GEMMs, K=256 = 16 k16-steps each ----
    const u32 lbase = (u32)(wc * 512 + lane * 16);
    #pragma unroll 1
    for (int g = 0; g < 2; ++g) {
        u32 bq[2][16];
        {
            const u32* p0 = g_Wb + (u32)(g * 16) * 2048 + lbase;
            #pragma unroll
            for (int i = 0; i < 4; ++i)
                *(uint4*)&bq[0][i * 4] = __ldg((const uint4*)(p0 + i * 4));
        }

        u32 ah[2][4];
        #pragma unroll 2
        for (int ks = 0; ks < 16; ++ks) {
            const int cur = ks & 1;
            // A fragments for this step
            const u32 aoff = (lane & 15) * AS + (ks * 16 + ((lane >> 4) << 3)) * 2
                           + wr * 32 * AS;
            ldm4(ah[0], sb + OFF_AHI + aoff);
            ldm4(ah[1], sb + OFF_AHI + 16 * AS + aoff);
            // prefetch next step's B fragments (4 x LDG.128)
            if (ks < 15) {
                const u32* pn = g_Wb + (u32)(g * 16 + ks + 1) * 2048 + lbase;
                #pragma unroll
                for (int i = 0; i < 4; ++i)
                    *(uint4*)&bq[cur ^ 1][i * 4] = __ldg((const uint4*)(pn + i * 4));
            }
            // 16 MMAs: 2 mt x 8 nt
            #pragma unroll
            for (int mt = 0; mt < 2; ++mt)
                #pragma unroll
                for (int j = 0; j < 8; ++j)
                    mma16816(acc[mt][j], ah[mt], &bq[cur][j * 2]);
        }

        // ---- GEMM boundary: h = relu(D1+b1) -> fp16 back into A ----
        if (g == 0) {
            __syncthreads();   // all warps done READING x before overwrite
            #pragma unroll
            for (int mt = 0; mt < 2; ++mt)
                #pragma unroll
                for (int j = 0; j < 8; ++j) {
                    float* a4 = acc[mt][j];
                    int r  = wr * 32 + mt * 16 + (lane >> 2);
                    int cc = wc * 64 + j * 8 + (lane & 3) * 2;
                    float bx = sb1[cc], by = sb1[cc + 1];
                    float h0 = fmaxf(a4[0] + bx, 0.f), h1 = fmaxf(a4[1] + by, 0.f);
                    float h2 = fmaxf(a4[2] + bx, 0.f), h3 = fmaxf(a4[3] + by, 0.f);
                    __half2 hiA = __floats2half2_rn(h0, h1);
                    __half2 hiB = __floats2half2_rn(h2, h3);
                    *(__half2*)(smem + OFF_AHI + r * AS + cc * 2)       = hiA;
                    *(__half2*)(smem + OFF_AHI + (r + 8) * AS + cc * 2) = hiB;
                }
            __syncthreads();   // h visible to all warps before GEMM2
            #pragma unroll
            for (int i = 0; i < 2; ++i)
                #pragma unroll
                for (int j = 0; j < 8; ++j)
                    #pragma unroll
                    for (int q = 0; q < 4; ++q) acc[i][j][q] = 0.f;
        }
    }

    // ---- final epilogue: g = h * sigmoid(D2+b2); g overlays A region ----
    float* gt = (float*)smem;   // [64][264] fp32 over A region
    {
        float gv[2][8][4];
        #pragma unroll
        for (int mt = 0; mt < 2; ++mt)
            #pragma unroll
            for (int j = 0; j < 8; ++j) {
                float* a4 = acc[mt][j];
                int r  = wr * 32 + mt * 16 + (lane >> 2);
                int cc = wc * 64 + j * 8 + (lane & 3) * 2;
                float bx = sb2[cc], by = sb2[cc + 1];
                float2 hA = __half22float2(*(__half2*)(smem + OFF_AHI + r * AS + cc * 2));
                float2 hB = __half22float2(*(__half2*)(smem + OFF_AHI + (r + 8) * AS + cc * 2));
                gv[mt][j][0] = hA.x / (1.f + __expf(-(a4[0] + bx)));
                gv[mt][j][1] = hA.y / (1.f + __expf(-(a4[1] + by)));
                gv[mt][j][2] = hB.x / (1.f + __expf(-(a4[2] + bx)));
                gv[mt][j][3] = hB.y / (1.f + __expf(-(a4[3] + by)));
            }
        __syncthreads();   // everyone done reading h before overwrite
        #pragma unroll
        for (int mt = 0; mt < 2; ++mt)
            #pragma unroll
            for (int j = 0; j < 8; ++j) {
                int r  = wr * 32 + mt * 16 + (lane >> 2);
                int cc = wc * 64 + j * 8 + (lane & 3) * 2;
                *(float2*)&gt[r * 264 + cc]       = make_float2(gv[mt][j][0], gv[mt][j][1]);
                *(float2*)&gt[(r + 8) * 264 + cc] = make_float2(gv[mt][j][2], gv[mt][j][3]);
            }
    }
    __syncthreads();

    // ---- segment reduction: sorted batch -> runs; one thread per column ----
    {
        const int ccol = tid;              // 256 threads = 256 columns
        int cur = bseg[0];
        float rsum = 0.f, rmax = 0.f;
        #pragma unroll 4
        for (int r = 0; r < BM; ++r) {
            int s = bseg[r];
            float g = gt[r * 264 + ccol];
            if (s != cur) {
                if (cur >= 0) {
                    atomicAdd(&out[(size_t)cur * 2 * H + H + ccol], rsum);
                    atomicMax((unsigned int*)&out[(size_t)cur * 2 * H + ccol],
                              __float_as_uint(rmax));   // g >= 0 always
                }
                cur = s; rsum = 0.f; rmax = 0.f;
            }
            if (s >= 0) { rsum += g; rmax = fmaxf(rmax, g); }
        }
        if (cur >= 0) {
            atomicAdd(&out[(size_t)cur * 2 * H + H + ccol], rsum);
            atomicMax((unsigned int*)&out[(size_t)cur * 2 * H + ccol],
                      __float_as_uint(rmax));
        }
    }
}

// ---------------------------------------------------------------------------
// Kernel 3: mean = sum / count. Count per segment via binary search on the
// sorted batch (one block per segment; thread 0 searches, block scales).
// ---------------------------------------------------------------------------
__global__ void finalize_kernel(float* out, const void* batch, int N) {
    __shared__ float inv;
    int seg = blockIdx.x;
    if (threadIdx.x == 0) {
        int lb, ub;
        if (g_is64) {
            const long long* b = (const long long*)batch;
            int lo = 0, hi = N;
            while (lo < hi) { int m = (lo + hi) >> 1; if (b[m] < (long long)seg) lo = m + 1; else hi = m; }
            lb = lo;
            lo = lb; hi = N;
            while (lo < hi) { int m = (lo + hi) >> 1; if (b[m] < (long long)(seg + 1)) lo = m + 1; else hi = m; }
            ub = lo;
        } else {
            const int* b = (const int*)batch;
            int lo = 0, hi = N;
            while (lo < hi) { int m = (lo + hi) >> 1; if (b[m] < seg) lo = m + 1; else hi = m; }
            lb = lo;
            lo = lb; hi = N;
            while (lo < hi) { int m = (lo + hi) >> 1; if (b[m] < seg + 1) lo = m + 1; else hi = m; }
            ub = lo;
        }
        int cnt = ub - lb;
        inv = cnt > 0 ? 1.0f / (float)cnt : 1.0f;
    }
    __syncthreads();
    out[(size_t)seg * 2 * H + H + threadIdx.x] *= inv;
}

extern "C" void kernel_launch(void* const* d_in, const int* in_sizes, int n_in,
                              void* d_out, int out_size) {
    const float* x     = (const float*)d_in[0];
    const void*  batch = d_in[1];
    const float* W1    = (const float*)d_in[2];
    const float* b1    = (const float*)d_in[3];
    const float* W2    = (const float*)d_in[4];
    const float* b2    = (const float*)d_in[5];
    float* out = (float*)d_out;

    int N = in_sizes[0] / H;

    cudaFuncSetAttribute(fused_kernel,
                         cudaFuncAttributeMaxDynamicSharedMemorySize, SMEM_TOTAL);

    prep_kernel<<<512, 256>>>(W1, W2, out, batch, N);

    int nblk = (N + BM - 1) / BM;
    fused_kernel<<<nblk, 256, SMEM_TOTAL>>>(x, batch, b1, b2, out, N);

    finalize_kernel<<<NSEG, 256>>>(out, batch, N);
}

// round 13
// speedup vs baseline: 1.2513x; 1.2513x over previous
#include <cuda_runtime.h>
#include <cuda_fp16.h>
#include <cstdint>
#include <math.h>

#define H 256
#define BM 64
#define NSEG 512
#define AS 528           // A row stride in bytes (264 fp16, padded)

typedef unsigned long long u64;
typedef unsigned int       u32;

// -------- device scratch (no allocations allowed) --------
__device__ int g_is64;
// W (fp16) packed in per-lane b-fragment layout (R11, coalesced LDG.64):
// [gemm(2)][kchunk(4)] blocks of 8192 u32 = [ks(4)][nt(32)][lane(32)][reg(2)]
__device__ __align__(16) u32 g_Wb[65536];

// -------- SMEM layout (bytes) --------
#define OFF_AHI   0                    // [64][264] fp16 = 33792
#define OFF_BSEG  67584                // 64 ints (gtile fp32 uses 0..67583)
#define OFF_BIAS  67840                // b1[256], b2[256] fp32 = 2048
#define SMEM_TOTAL 69888
// g tile (final): fp32 [64][264] overlays bytes 0..67583 (A dead by then)

// -------- PTX helpers (legal on plain sm_103 target) --------
__device__ __forceinline__ void ldm4(u32* r, u32 addr) {
    asm volatile("ldmatrix.sync.aligned.m8n8.x4.shared.b16 {%0,%1,%2,%3},[%4];"
        : "=r"(r[0]), "=r"(r[1]), "=r"(r[2]), "=r"(r[3]) : "r"(addr));
}
__device__ __forceinline__ void mma16816(float* d, const u32* a, const u32* b) {
    asm volatile(
        "mma.sync.aligned.m16n8k16.row.col.f32.f16.f16.f32 "
        "{%0,%1,%2,%3},{%4,%5,%6,%7},{%8,%9},{%0,%1,%2,%3};"
        : "+f"(d[0]), "+f"(d[1]), "+f"(d[2]), "+f"(d[3])
        : "r"(a[0]), "r"(a[1]), "r"(a[2]), "r"(a[3]), "r"(b[0]), "r"(b[1]));
}

// ---------------------------------------------------------------------------
// Kernel 1: W prep (fp32 -> fp16, b-fragment layout) + zero out + batch
// dtype detection. 512 blocks x 256 threads.
// ---------------------------------------------------------------------------
__global__ void prep_kernel(const float* __restrict__ W1,
                            const float* __restrict__ W2,
                            float* out,
                            const void* batch, int N) {
    int id = blockIdx.x * 256 + threadIdx.x;     // 131072 total
    // zero output (262144 floats)
    out[id] = 0.0f;
    out[id + 131072] = 0.0f;
    if (id == 0) {
        const int* bw = (const int*)batch;
        int o = ((N - 1) & 1) ? (N - 1) : (N - 2);
        int orv = 0;
        if (o >= 4) orv = bw[o] | bw[o - 2] | bw[o - 4];
        else if (o >= 0) orv = bw[o];
        g_is64 = (orv == 0) ? 1 : 0;
    }
    // W pack (R11 layout)
    int gemm = id >> 16, rem = id & 65535;
    int n = rem >> 8, k = rem & 255;
    float w = (gemm ? W2 : W1)[n * H + k];
    __half hi = __float2half_rn(w);
    int chunk = k >> 6, ks = (k >> 4) & 3, kk = k & 15;
    int nt = n >> 3, nn = n & 7;
    int lane = nn * 4 + ((kk & 7) >> 1);
    int reg  = kk >> 3;
    int half_i = kk & 1;
    u32 base = (u32)((gemm * 4 + chunk) * 8192
                     + ((ks * 32 + nt) * 32 + lane) * 2 + reg);
    __half* wb = (__half*)g_Wb;
    wb[(size_t)base * 2 + half_i] = hi;
}

// ---------------------------------------------------------------------------
// Kernel 2: fused  relu(xW1^T+b1) -> sigmoid(hW2^T+b2) gate -> segment reduce.
// Plain fp16 HMMA, warp grid 2x4, full k16-step mainloop with full-step
// B double-buffer via __ldg (R11 coalesced layout). No counts work here.
// ---------------------------------------------------------------------------
extern "C" __global__ void __launch_bounds__(256, 2)
fused_kernel(const float* __restrict__ x, const void* __restrict__ batch,
             const float* __restrict__ b1, const float* __restrict__ b2,
             float* __restrict__ out, int N)
{
    extern __shared__ char smem[];
    const u32 sb = (u32)__cvta_generic_to_shared(smem);
    const int tid  = threadIdx.x;
    const int w    = tid >> 5;
    const int lane = tid & 31;
    const int wr   = w >> 2;            // 0..1: row group (32 rows)
    const int wc   = w & 3;             // 0..3: col group (64 cols)
    const int row0 = blockIdx.x * BM;
    float* sb1 = (float*)(smem + OFF_BIAS);
    float* sb2 = sb1 + H;
    int* bseg = (int*)(smem + OFF_BSEG);

    // ---- bias + segment ids ----
    sb1[tid] = b1[tid];
    sb2[tid] = b2[tid];
    if (tid < BM) {
        int r = row0 + tid;
        int s = -1;
        if (r < N) {
            if (g_is64) s = (int)((const long long*)batch)[r];
            else        s = ((const int*)batch)[r];
        }
        bseg[tid] = s;
    }

    // ---- load x tile fp32 -> fp16 into AHI ([64][264] padded) ----
    {
        const float4* xg = (const float4*)x;
        #pragma unroll
        for (int it = 0; it < 16; ++it) {
            int f = tid + it * 256;            // 4096 float4s
            int r = f >> 6, k4 = f & 63;
            float4 v = make_float4(0.f, 0.f, 0.f, 0.f);
            if (row0 + r < N) v = xg[(size_t)(row0 + r) * (H / 4) + k4];
            __half2 h01 = __floats2half2_rn(v.x, v.y);
            __half2 h23 = __floats2half2_rn(v.z, v.w);
            char* pa = smem + OFF_AHI + r * AS + k4 * 8;
            *(__half2*)pa = h01;  *(__half2*)(pa + 4) = h23;
        }
    }
    __syncthreads();   // x tile visible to all warps

    float acc[2][8][4];
    #pragma unroll
    for (int i = 0; i < 2; ++i)
        #pragma unroll
        for (int j = 0; j < 8; ++j)
            #pragma unroll
            for (int q = 0; q < 4; ++q) acc[i][j][q] = 0.f;

    // ---- 2 GEMMs, K=256 = 16 full k16-steps each ----
    #pragma unroll 1
    for (int g = 0; g < 2; ++g) {
        const u32* bb = g_Wb + g * 32768;                 // fp16 W blocks
        const u32 lwo = (u32)(wc * 512 + lane * 2);       // nt = wc*8 base

        uint2 bh[2][8];
        // preload step 0 (all 8 nt fragments)
        #pragma unroll
        for (int j = 0; j < 8; ++j)
            bh[0][j] = __ldg((const uint2*)(bb + lwo + j * 64));

        u32 ah[2][4];
        #pragma unroll 2
        for (int ks = 0; ks < 16; ++ks) {
            const int cur = ks & 1;
            // A fragments for this step
            const u32 aoff = (lane & 15) * AS + (ks * 16 + ((lane >> 4) << 3)) * 2
                           + wr * 32 * AS;
            ldm4(ah[0], sb + OFF_AHI + aoff);
            ldm4(ah[1], sb + OFF_AHI + 16 * AS + aoff);
            // prefetch next full step's B fragments
            if (ks < 15) {
                int k1 = ks + 1;
                u32 ob = (u32)(k1 >> 2) * 8192 + (u32)(k1 & 3) * 2048 + lwo;
                #pragma unroll
                for (int j = 0; j < 8; ++j)
                    bh[cur ^ 1][j] = __ldg((const uint2*)(bb + ob + j * 64));
            }
            // 16 MMAs: 2 mt x 8 nt
            #pragma unroll
            for (int mt = 0; mt < 2; ++mt)
                #pragma unroll
                for (int j = 0; j < 8; ++j)
                    mma16816(acc[mt][j], ah[mt], (const u32*)&bh[cur][j]);
        }

        // ---- GEMM boundary: h = relu(D1+b1) -> fp16 back into A ----
        if (g == 0) {
            __syncthreads();   // all warps done READING x before overwrite
            #pragma unroll
            for (int mt = 0; mt < 2; ++mt)
                #pragma unroll
                for (int j = 0; j < 8; ++j) {
                    float* a4 = acc[mt][j];
                    int r  = wr * 32 + mt * 16 + (lane >> 2);
                    int cc = wc * 64 + j * 8 + (lane & 3) * 2;
                    float bx = sb1[cc], by = sb1[cc + 1];
                    float h0 = fmaxf(a4[0] + bx, 0.f), h1 = fmaxf(a4[1] + by, 0.f);
                    float h2 = fmaxf(a4[2] + bx, 0.f), h3 = fmaxf(a4[3] + by, 0.f);
                    __half2 hiA = __floats2half2_rn(h0, h1);
                    __half2 hiB = __floats2half2_rn(h2, h3);
                    *(__half2*)(smem + OFF_AHI + r * AS + cc * 2)       = hiA;
                    *(__half2*)(smem + OFF_AHI + (r + 8) * AS + cc * 2) = hiB;
                }
            __syncthreads();   // h visible to all warps before GEMM2
            #pragma unroll
            for (int i = 0; i < 2; ++i)
                #pragma unroll
                for (int j = 0; j < 8; ++j)
                    #pragma unroll
                    for (int q = 0; q < 4; ++q) acc[i][j][q] = 0.f;
        }
    }

    // ---- final epilogue: g = h * sigmoid(D2+b2); g overlays A region ----
    float* gt = (float*)smem;   // [64][264] fp32 over A region
    {
        float gv[2][8][4];
        #pragma unroll
        for (int mt = 0; mt < 2; ++mt)
            #pragma unroll
            for (int j = 0; j < 8; ++j) {
                float* a4 = acc[mt][j];
                int r  = wr * 32 + mt * 16 + (lane >> 2);
                int cc = wc * 64 + j * 8 + (lane & 3) * 2;
                float bx = sb2[cc], by = sb2[cc + 1];
                float2 hA = __half22float2(*(__half2*)(smem + OFF_AHI + r * AS + cc * 2));
                float2 hB = __half22float2(*(__half2*)(smem + OFF_AHI + (r + 8) * AS + cc * 2));
                gv[mt][j][0] = hA.x / (1.f + __expf(-(a4[0] + bx)));
                gv[mt][j][1] = hA.y / (1.f + __expf(-(a4[1] + by)));
                gv[mt][j][2] = hB.x / (1.f + __expf(-(a4[2] + bx)));
                gv[mt][j][3] = hB.y / (1.f + __expf(-(a4[3] + by)));
            }
        __syncthreads();   // everyone done reading h before overwrite
        #pragma unroll
        for (int mt = 0; mt < 2; ++mt)
            #pragma unroll
            for (int j = 0; j < 8; ++j) {
                int r  = wr * 32 + mt * 16 + (lane >> 2);
                int cc = wc * 64 + j * 8 + (lane & 3) * 2;
                *(float2*)&gt[r * 264 + cc]       = make_float2(gv[mt][j][0], gv[mt][j][1]);
                *(float2*)&gt[(r + 8) * 264 + cc] = make_float2(gv[mt][j][2], gv[mt][j][3]);
            }
    }
    __syncthreads();

    // ---- segment reduction: sorted batch -> runs; one thread per column ----
    {
        const int ccol = tid;              // 256 threads = 256 columns
        int cur = bseg[0];
        float rsum = 0.f, rmax = 0.f;
        #pragma unroll 1
        for (int r = 0; r < BM; ++r) {
            int s = bseg[r];
            float g = gt[r * 264 + ccol];
            if (s != cur) {
                if (cur >= 0) {
                    atomicAdd(&out[(size_t)cur * 2 * H + H + ccol], rsum);
                    atomicMax((unsigned int*)&out[(size_t)cur * 2 * H + ccol],
                              __float_as_uint(rmax));   // g >= 0 always
                }
                cur = s; rsum = 0.f; rmax = 0.f;
            }
            if (s >= 0) { rsum += g; rmax = fmaxf(rmax, g); }
        }
        if (cur >= 0) {
            atomicAdd(&out[(size_t)cur * 2 * H + H + ccol], rsum);
            atomicMax((unsigned int*)&out[(size_t)cur * 2 * H + ccol],
                      __float_as_uint(rmax));
        }
    }
}

// ---------------------------------------------------------------------------
// Kernel 3: mean = sum / count. Count per segment via binary search on the
// sorted batch (one block per segment; thread 0 searches, block scales).
// ---------------------------------------------------------------------------
__global__ void finalize_kernel(float* out, const void* batch, int N) {
    __shared__ float inv;
    int seg = blockIdx.x;
    if (threadIdx.x == 0) {
        int lb, ub;
        if (g_is64) {
            const long long* b = (const long long*)batch;
            int lo = 0, hi = N;
            while (lo < hi) { int m = (lo + hi) >> 1; if (b[m] < (long long)seg) lo = m + 1; else hi = m; }
            lb = lo;
            lo = lb; hi = N;
            while (lo < hi) { int m = (lo + hi) >> 1; if (b[m] < (long long)(seg + 1)) lo = m + 1; else hi = m; }
            ub = lo;
        } else {
            const int* b = (const int*)batch;
            int lo = 0, hi = N;
            while (lo < hi) { int m = (lo + hi) >> 1; if (b[m] < seg) lo = m + 1; else hi = m; }
            lb = lo;
            lo = lb; hi = N;
            while (lo < hi) { int m = (lo + hi) >> 1; if (b[m] < seg + 1) lo = m + 1; else hi = m; }
            ub = lo;
        }
        int cnt = ub - lb;
        inv = cnt > 0 ? 1.0f / (float)cnt : 1.0f;
    }
    __syncthreads();
    out[(size_t)seg * 2 * H + H + threadIdx.x] *= inv;
}

extern "C" void kernel_launch(void* const* d_in, const int* in_sizes, int n_in,
                              void* d_out, int out_size) {
    const float* x     = (const float*)d_in[0];
    const void*  batch = d_in[1];
    const float* W1    = (const float*)d_in[2];
    const float* b1    = (const float*)d_in[3];
    const float* W2    = (const float*)d_in[4];
    const float* b2    = (const float*)d_in[5];
    float* out = (float*)d_out;

    int N = in_sizes[0] / H;

    cudaFuncSetAttribute(fused_kernel,
                         cudaFuncAttributeMaxDynamicSharedMemorySize, SMEM_TOTAL);

    prep_kernel<<<512, 256>>>(W1, W2, out, batch, N);

    int nblk = (N + BM - 1) / BM;
    fused_kernel<<<nblk, 256, SMEM_TOTAL>>>(x, batch, b1, b2, out, N);

    finalize_kernel<<<NSEG, 256>>>(out, batch, N);
}

// round 14
// speedup vs baseline: 1.3083x; 1.0455x over previous
#include <cuda_runtime.h>
#include <cuda_fp16.h>
#include <cstdint>
#include <math.h>

#define H 256
#define BM 64
#define NSEG 512
#define AS 528           // A row stride in bytes (264 fp16, padded)

typedef unsigned long long u64;
typedef unsigned int       u32;

// -------- device scratch (no allocations allowed) --------
__device__ int g_is64;
// W (fp16) packed in per-lane b-fragment layout (coalesced LDG.64):
// [gemm(2)][kchunk(4)] blocks of 8192 u32 = [ks(4)][nt(32)][lane(32)][reg(2)]
__device__ __align__(16) u32 g_Wb[65536];

// -------- SMEM layout (bytes) --------
#define OFF_AHI   0                    // [64][264] fp16 = 33792
#define OFF_BSEG  67584                // 64 ints (gtile fp32 uses 0..67583)
#define OFF_BIAS  67840                // b1[256], b2[256] fp32 = 2048
#define SMEM_TOTAL 69888
// g tile (final): fp32 [64][264] overlays bytes 0..67583 (A dead by then)

// -------- PTX helpers (legal on plain sm_103 target) --------
__device__ __forceinline__ void ldm4(u32* r, u32 addr) {
    asm volatile("ldmatrix.sync.aligned.m8n8.x4.shared.b16 {%0,%1,%2,%3},[%4];"
        : "=r"(r[0]), "=r"(r[1]), "=r"(r[2]), "=r"(r[3]) : "r"(addr));
}
__device__ __forceinline__ void mma16816(float* d, const u32* a, const u32* b) {
    asm volatile(
        "mma.sync.aligned.m16n8k16.row.col.f32.f16.f16.f32 "
        "{%0,%1,%2,%3},{%4,%5,%6,%7},{%8,%9},{%0,%1,%2,%3};"
        : "+f"(d[0]), "+f"(d[1]), "+f"(d[2]), "+f"(d[3])
        : "r"(a[0]), "r"(a[1]), "r"(a[2]), "r"(a[3]), "r"(b[0]), "r"(b[1]));
}

// ---------------------------------------------------------------------------
// Kernel 1: W prep (fp32 -> fp16, b-fragment layout) + zero out + batch
// dtype detection. 512 blocks x 256 threads.
// ---------------------------------------------------------------------------
__global__ void prep_kernel(const float* __restrict__ W1,
                            const float* __restrict__ W2,
                            float* out,
                            const void* batch, int N) {
    int id = blockIdx.x * 256 + threadIdx.x;     // 131072 total
    // zero output (262144 floats)
    out[id] = 0.0f;
    out[id + 131072] = 0.0f;
    if (id == 0) {
        const int* bw = (const int*)batch;
        int o = ((N - 1) & 1) ? (N - 1) : (N - 2);
        int orv = 0;
        if (o >= 4) orv = bw[o] | bw[o - 2] | bw[o - 4];
        else if (o >= 0) orv = bw[o];
        g_is64 = (orv == 0) ? 1 : 0;
    }
    // W pack
    int gemm = id >> 16, rem = id & 65535;
    int n = rem >> 8, k = rem & 255;
    float w = (gemm ? W2 : W1)[n * H + k];
    __half hi = __float2half_rn(w);
    int chunk = k >> 6, ks = (k >> 4) & 3, kk = k & 15;
    int nt = n >> 3, nn = n & 7;
    int lane = nn * 4 + ((kk & 7) >> 1);
    int reg  = kk >> 3;
    int half_i = kk & 1;
    u32 base = (u32)((gemm * 4 + chunk) * 8192
                     + ((ks * 32 + nt) * 32 + lane) * 2 + reg);
    __half* wb = (__half*)g_Wb;
    wb[(size_t)base * 2 + half_i] = hi;
}

// ---------------------------------------------------------------------------
// Kernel 2: fused  relu(xW1^T+b1) -> sigmoid(hW2^T+b2) gate -> segment reduce.
// Plain fp16 HMMA. Warp grid 1x8: each warp owns ALL 64 rows (mt=4) and a
// distinct 32-col slice (nt=4) -> ZERO B duplication across warps (B L2
// traffic halves vs 2x4 grid). Full-step B double-buffer via __ldg.
// ---------------------------------------------------------------------------
extern "C" __global__ void __launch_bounds__(256, 2)
fused_kernel(const float* __restrict__ x, const void* __restrict__ batch,
             const float* __restrict__ b1, const float* __restrict__ b2,
             float* __restrict__ out, int N)
{
    extern __shared__ char smem[];
    const u32 sb = (u32)__cvta_generic_to_shared(smem);
    const int tid  = threadIdx.x;
    const int w    = tid >> 5;          // warp 0..7: output cols w*32..w*32+31
    const int lane = tid & 31;
    const int row0 = blockIdx.x * BM;
    float* sb1 = (float*)(smem + OFF_BIAS);
    float* sb2 = sb1 + H;
    int* bseg = (int*)(smem + OFF_BSEG);

    // ---- bias + segment ids ----
    sb1[tid] = b1[tid];
    sb2[tid] = b2[tid];
    if (tid < BM) {
        int r = row0 + tid;
        int s = -1;
        if (r < N) {
            if (g_is64) s = (int)((const long long*)batch)[r];
            else        s = ((const int*)batch)[r];
        }
        bseg[tid] = s;
    }

    // ---- load x tile fp32 -> fp16 into AHI ([64][264] padded) ----
    {
        const float4* xg = (const float4*)x;
        #pragma unroll
        for (int it = 0; it < 16; ++it) {
            int f = tid + it * 256;            // 4096 float4s
            int r = f >> 6, k4 = f & 63;
            float4 v = make_float4(0.f, 0.f, 0.f, 0.f);
            if (row0 + r < N) v = xg[(size_t)(row0 + r) * (H / 4) + k4];
            __half2 h01 = __floats2half2_rn(v.x, v.y);
            __half2 h23 = __floats2half2_rn(v.z, v.w);
            char* pa = smem + OFF_AHI + r * AS + k4 * 8;
            *(__half2*)pa = h01;  *(__half2*)(pa + 4) = h23;
        }
    }
    __syncthreads();   // x tile visible to all warps

    float acc[4][4][4];
    #pragma unroll
    for (int i = 0; i < 4; ++i)
        #pragma unroll
        for (int j = 0; j < 4; ++j)
            #pragma unroll
            for (int q = 0; q < 4; ++q) acc[i][j][q] = 0.f;

    // ---- 2 GEMMs, K=256 = 16 full k16-steps each ----
    #pragma unroll 1
    for (int g = 0; g < 2; ++g) {
        const u32* bb = g_Wb + g * 32768;                 // fp16 W blocks
        const u32 lwo = (u32)(w * 256 + lane * 2);        // nt = w*4 base

        uint2 bh[2][4];
        // preload step 0 (4 nt fragments)
        #pragma unroll
        for (int j = 0; j < 4; ++j)
            bh[0][j] = __ldg((const uint2*)(bb + lwo + j * 64));

        u32 ah[4][4];
        #pragma unroll 2
        for (int ks = 0; ks < 16; ++ks) {
            const int cur = ks & 1;
            // A fragments for this step (4 row-tiles)
            const u32 aoff = (lane & 15) * AS + (ks * 16 + ((lane >> 4) << 3)) * 2;
            #pragma unroll
            for (int mt = 0; mt < 4; ++mt)
                ldm4(ah[mt], sb + OFF_AHI + mt * 16 * AS + aoff);
            // prefetch next full step's B fragments
            if (ks < 15) {
                int k1 = ks + 1;
                u32 ob = (u32)(k1 >> 2) * 8192 + (u32)(k1 & 3) * 2048 + lwo;
                #pragma unroll
                for (int j = 0; j < 4; ++j)
                    bh[cur ^ 1][j] = __ldg((const uint2*)(bb + ob + j * 64));
            }
            // 16 MMAs: 4 mt x 4 nt
            #pragma unroll
            for (int mt = 0; mt < 4; ++mt)
                #pragma unroll
                for (int j = 0; j < 4; ++j)
                    mma16816(acc[mt][j], ah[mt], (const u32*)&bh[cur][j]);
        }

        // ---- GEMM boundary: h = relu(D1+b1) -> fp16 back into A ----
        if (g == 0) {
            __syncthreads();   // all warps done READING x before overwrite
            #pragma unroll
            for (int mt = 0; mt < 4; ++mt)
                #pragma unroll
                for (int j = 0; j < 4; ++j) {
                    float* a4 = acc[mt][j];
                    int r  = mt * 16 + (lane >> 2);
                    int cc = w * 32 + j * 8 + (lane & 3) * 2;
                    float bx = sb1[cc], by = sb1[cc + 1];
                    float h0 = fmaxf(a4[0] + bx, 0.f), h1 = fmaxf(a4[1] + by, 0.f);
                    float h2 = fmaxf(a4[2] + bx, 0.f), h3 = fmaxf(a4[3] + by, 0.f);
                    __half2 hiA = __floats2half2_rn(h0, h1);
                    __half2 hiB = __floats2half2_rn(h2, h3);
                    *(__half2*)(smem + OFF_AHI + r * AS + cc * 2)       = hiA;
                    *(__half2*)(smem + OFF_AHI + (r + 8) * AS + cc * 2) = hiB;
                }
            __syncthreads();   // h visible to all warps before GEMM2
            #pragma unroll
            for (int i = 0; i < 4; ++i)
                #pragma unroll
                for (int j = 0; j < 4; ++j)
                    #pragma unroll
                    for (int q = 0; q < 4; ++q) acc[i][j][q] = 0.f;
        }
    }

    // ---- final epilogue: g = h * sigmoid(D2+b2); g overlays A region ----
    float* gt = (float*)smem;   // [64][264] fp32 over A region
    {
        float gv[4][4][4];
        #pragma unroll
        for (int mt = 0; mt < 4; ++mt)
            #pragma unroll
            for (int j = 0; j < 4; ++j) {
                float* a4 = acc[mt][j];
                int r  = mt * 16 + (lane >> 2);
                int cc = w * 32 + j * 8 + (lane & 3) * 2;
                float bx = sb2[cc], by = sb2[cc + 1];
                float2 hA = __half22float2(*(__half2*)(smem + OFF_AHI + r * AS + cc * 2));
                float2 hB = __half22float2(*(__half2*)(smem + OFF_AHI + (r + 8) * AS + cc * 2));
                gv[mt][j][0] = hA.x / (1.f + __expf(-(a4[0] + bx)));
                gv[mt][j][1] = hA.y / (1.f + __expf(-(a4[1] + by)));
                gv[mt][j][2] = hB.x / (1.f + __expf(-(a4[2] + bx)));
                gv[mt][j][3] = hB.y / (1.f + __expf(-(a4[3] + by)));
            }
        __syncthreads();   // everyone done reading h before overwrite
        #pragma unroll
        for (int mt = 0; mt < 4; ++mt)
            #pragma unroll
            for (int j = 0; j < 4; ++j) {
                int r  = mt * 16 + (lane >> 2);
                int cc = w * 32 + j * 8 + (lane & 3) * 2;
                *(float2*)&gt[r * 264 + cc]       = make_float2(gv[mt][j][0], gv[mt][j][1]);
                *(float2*)&gt[(r + 8) * 264 + cc] = make_float2(gv[mt][j][2], gv[mt][j][3]);
            }
    }
    __syncthreads();

    // ---- segment reduction: sorted batch -> runs; one thread per column ----
    {
        const int ccol = tid;              // 256 threads = 256 columns
        int cur = bseg[0];
        float rsum = 0.f, rmax = 0.f;
        #pragma unroll 1
        for (int r = 0; r < BM; ++r) {
            int s = bseg[r];
            float g = gt[r * 264 + ccol];
            if (s != cur) {
                if (cur >= 0) {
                    atomicAdd(&out[(size_t)cur * 2 * H + H + ccol], rsum);
                    atomicMax((unsigned int*)&out[(size_t)cur * 2 * H + ccol],
                              __float_as_uint(rmax));   // g >= 0 always
                }
                cur = s; rsum = 0.f; rmax = 0.f;
            }
            if (s >= 0) { rsum += g; rmax = fmaxf(rmax, g); }
        }
        if (cur >= 0) {
            atomicAdd(&out[(size_t)cur * 2 * H + H + ccol], rsum);
            atomicMax((unsigned int*)&out[(size_t)cur * 2 * H + ccol],
                      __float_as_uint(rmax));
        }
    }
}

// ---------------------------------------------------------------------------
// Kernel 3: mean = sum / count (count via binary search on sorted batch).
// ---------------------------------------------------------------------------
__global__ void finalize_kernel(float* out, const void* batch, int N) {
    __shared__ float inv;
    int seg = blockIdx.x;
    if (threadIdx.x == 0) {
        int lb, ub;
        if (g_is64) {
            const long long* b = (const long long*)batch;
            int lo = 0, hi = N;
            while (lo < hi) { int m = (lo + hi) >> 1; if (b[m] < (long long)seg) lo = m + 1; else hi = m; }
            lb = lo;
            lo = lb; hi = N;
            while (lo < hi) { int m = (lo + hi) >> 1; if (b[m] < (long long)(seg + 1)) lo = m + 1; else hi = m; }
            ub = lo;
        } else {
            const int* b = (const int*)batch;
            int lo = 0, hi = N;
            while (lo < hi) { int m = (lo + hi) >> 1; if (b[m] < seg) lo = m + 1; else hi = m; }
            lb = lo;
            lo = lb; hi = N;
            while (lo < hi) { int m = (lo + hi) >> 1; if (b[m] < seg + 1) lo = m + 1; else hi = m; }
            ub = lo;
        }
        int cnt = ub - lb;
        inv = cnt > 0 ? 1.0f / (float)cnt : 1.0f;
    }
    __syncthreads();
    out[(size_t)seg * 2 * H + H + threadIdx.x] *= inv;
}

// ---------------------------------------------------------------------------
// Kernel 4: no-op. Shifts global launch indexing so ncu's "-s 5 -c 1"
// captures fused_kernel (launch 5 = 2nd kernel of the 1st graph replay).
// ---------------------------------------------------------------------------
__global__ void noop_kernel() {}

extern "C" void kernel_launch(void* const* d_in, const int* in_sizes, int n_in,
                              void* d_out, int out_size) {
    const float* x     = (const float*)d_in[0];
    const void*  batch = d_in[1];
    const float* W1    = (const float*)d_in[2];
    const float* b1    = (const float*)d_in[3];
    const float* W2    = (const float*)d_in[4];
    const float* b2    = (const float*)d_in[5];
    float* out = (float*)d_out;

    int N = in_sizes[0] / H;

    cudaFuncSetAttribute(fused_kernel,
                         cudaFuncAttributeMaxDynamicSharedMemorySize, SMEM_TOTAL);

    prep_kernel<<<512, 256>>>(W1, W2, out, batch, N);

    int nblk = (N + BM - 1) / BM;
    fused_kernel<<<nblk, 256, SMEM_TOTAL>>>(x, batch, b1, b2, out, N);

    finalize_kernel<<<NSEG, 256>>>(out, batch, N);
    noop_kernel<<<1, 32>>>();
}

// round 15
// speedup vs baseline: 1.4954x; 1.1430x over previous
#include <cuda_runtime.h>
#include <cuda_fp16.h>
#include <cstdint>
#include <math.h>

#define H 256
#define BM 32
#define NSEG 512
#define AS 528           // A row stride in bytes (264 fp16, padded)

typedef unsigned long long u64;
typedef unsigned int       u32;

// -------- device scratch (no allocations allowed) --------
__device__ int g_is64;
// W (fp16) packed in per-lane b-fragment layout (coalesced LDG.64):
// [gemm(2)][kchunk(4)] blocks of 8192 u32 = [ks(4)][nt(32)][lane(32)][reg(2)]
__device__ __align__(16) u32 g_Wb[65536];

// -------- SMEM layout (bytes) --------
#define OFF_AHI   0                    // [32][264] fp16 = 16896
// g tile (final): fp32 [32][264] = 33792 bytes overlays 0..33791
#define OFF_BSEG  33792                // 32 ints = 128
#define OFF_BIAS  33920                // b1[256], b2[256] fp32 = 2048
#define SMEM_TOTAL 35968

// -------- PTX helpers (legal on plain sm_103 target) --------
__device__ __forceinline__ void ldm4(u32* r, u32 addr) {
    asm volatile("ldmatrix.sync.aligned.m8n8.x4.shared.b16 {%0,%1,%2,%3},[%4];"
        : "=r"(r[0]), "=r"(r[1]), "=r"(r[2]), "=r"(r[3]) : "r"(addr));
}
__device__ __forceinline__ void mma16816(float* d, const u32* a, const u32* b) {
    asm volatile(
        "mma.sync.aligned.m16n8k16.row.col.f32.f16.f16.f32 "
        "{%0,%1,%2,%3},{%4,%5,%6,%7},{%8,%9},{%0,%1,%2,%3};"
        : "+f"(d[0]), "+f"(d[1]), "+f"(d[2]), "+f"(d[3])
        : "r"(a[0]), "r"(a[1]), "r"(a[2]), "r"(a[3]), "r"(b[0]), "r"(b[1]));
}

// ---------------------------------------------------------------------------
// Kernel 1: W prep (fp32 -> fp16, b-fragment layout) + zero out + batch
// dtype detection. 512 blocks x 256 threads.
// ---------------------------------------------------------------------------
__global__ void prep_kernel(const float* __restrict__ W1,
                            const float* __restrict__ W2,
                            float* out,
                            const void* batch, int N) {
    int id = blockIdx.x * 256 + threadIdx.x;     // 131072 total
    // zero output (262144 floats)
    out[id] = 0.0f;
    out[id + 131072] = 0.0f;
    if (id == 0) {
        const int* bw = (const int*)batch;
        int o = ((N - 1) & 1) ? (N - 1) : (N - 2);
        int orv = 0;
        if (o >= 4) orv = bw[o] | bw[o - 2] | bw[o - 4];
        else if (o >= 0) orv = bw[o];
        g_is64 = (orv == 0) ? 1 : 0;
    }
    // W pack
    int gemm = id >> 16, rem = id & 65535;
    int n = rem >> 8, k = rem & 255;
    float w = (gemm ? W2 : W1)[n * H + k];
    __half hi = __float2half_rn(w);
    int chunk = k >> 6, ks = (k >> 4) & 3, kk = k & 15;
    int nt = n >> 3, nn = n & 7;
    int lane = nn * 4 + ((kk & 7) >> 1);
    int reg  = kk >> 3;
    int half_i = kk & 1;
    u32 base = (u32)((gemm * 4 + chunk) * 8192
                     + ((ks * 32 + nt) * 32 + lane) * 2 + reg);
    __half* wb = (__half*)g_Wb;
    wb[(size_t)base * 2 + half_i] = hi;
}

// ---------------------------------------------------------------------------
// Kernel 2: fused  relu(xW1^T+b1) -> sigmoid(hW2^T+b2) gate -> segment reduce.
// Plain fp16 HMMA. BM=32 tile, warp grid 1x8 (mt=2, nt=4): each warp owns
// all 32 rows and a distinct 32-col slice (no B duplication). Small footprint
// (36KB smem, ~78 regs) -> 3 CTAs/SM = 6 warps/SMSP for latency hiding.
// ---------------------------------------------------------------------------
extern "C" __global__ void __launch_bounds__(256, 3)
fused_kernel(const float* __restrict__ x, const void* __restrict__ batch,
             const float* __restrict__ b1, const float* __restrict__ b2,
             float* __restrict__ out, int N)
{
    extern __shared__ char smem[];
    const u32 sb = (u32)__cvta_generic_to_shared(smem);
    const int tid  = threadIdx.x;
    const int w    = tid >> 5;          // warp 0..7: output cols w*32..w*32+31
    const int lane = tid & 31;
    const int row0 = blockIdx.x * BM;
    float* sb1 = (float*)(smem + OFF_BIAS);
    float* sb2 = sb1 + H;
    int* bseg = (int*)(smem + OFF_BSEG);

    // ---- bias + segment ids ----
    sb1[tid] = b1[tid];
    sb2[tid] = b2[tid];
    if (tid < BM) {
        int r = row0 + tid;
        int s = -1;
        if (r < N) {
            if (g_is64) s = (int)((const long long*)batch)[r];
            else        s = ((const int*)batch)[r];
        }
        bseg[tid] = s;
    }

    // ---- load x tile fp32 -> fp16 into AHI ([32][264] padded) ----
    {
        const float4* xg = (const float4*)x;
        #pragma unroll
        for (int it = 0; it < 8; ++it) {
            int f = tid + it * 256;            // 2048 float4s
            int r = f >> 6, k4 = f & 63;
            float4 v = make_float4(0.f, 0.f, 0.f, 0.f);
            if (row0 + r < N) v = xg[(size_t)(row0 + r) * (H / 4) + k4];
            __half2 h01 = __floats2half2_rn(v.x, v.y);
            __half2 h23 = __floats2half2_rn(v.z, v.w);
            char* pa = smem + OFF_AHI + r * AS + k4 * 8;
            *(__half2*)pa = h01;  *(__half2*)(pa + 4) = h23;
        }
    }
    __syncthreads();   // x tile visible to all warps

    float acc[2][4][4];
    #pragma unroll
    for (int i = 0; i < 2; ++i)
        #pragma unroll
        for (int j = 0; j < 4; ++j)
            #pragma unroll
            for (int q = 0; q < 4; ++q) acc[i][j][q] = 0.f;

    // ---- 2 GEMMs, K=256 = 16 full k16-steps each ----
    #pragma unroll 1
    for (int g = 0; g < 2; ++g) {
        const u32* bb = g_Wb + g * 32768;                 // fp16 W blocks
        const u32 lwo = (u32)(w * 256 + lane * 2);        // nt = w*4 base

        uint2 bh[2][4];
        // preload step 0 (4 nt fragments)
        #pragma unroll
        for (int j = 0; j < 4; ++j)
            bh[0][j] = __ldg((const uint2*)(bb + lwo + j * 64));

        u32 ah[2][4];
        #pragma unroll 2
        for (int ks = 0; ks < 16; ++ks) {
            const int cur = ks & 1;
            // A fragments for this step (2 row-tiles)
            const u32 aoff = (lane & 15) * AS + (ks * 16 + ((lane >> 4) << 3)) * 2;
            ldm4(ah[0], sb + OFF_AHI + aoff);
            ldm4(ah[1], sb + OFF_AHI + 16 * AS + aoff);
            // prefetch next full step's B fragments
            if (ks < 15) {
                int k1 = ks + 1;
                u32 ob = (u32)(k1 >> 2) * 8192 + (u32)(k1 & 3) * 2048 + lwo;
                #pragma unroll
                for (int j = 0; j < 4; ++j)
                    bh[cur ^ 1][j] = __ldg((const uint2*)(bb + ob + j * 64));
            }
            // 8 MMAs: 2 mt x 4 nt
            #pragma unroll
            for (int mt = 0; mt < 2; ++mt)
                #pragma unroll
                for (int j = 0; j < 4; ++j)
                    mma16816(acc[mt][j], ah[mt], (const u32*)&bh[cur][j]);
        }

        // ---- GEMM boundary: h = relu(D1+b1) -> fp16 back into A ----
        if (g == 0) {
            __syncthreads();   // all warps done READING x before overwrite
            #pragma unroll
            for (int mt = 0; mt < 2; ++mt)
                #pragma unroll
                for (int j = 0; j < 4; ++j) {
                    float* a4 = acc[mt][j];
                    int r  = mt * 16 + (lane >> 2);
                    int cc = w * 32 + j * 8 + (lane & 3) * 2;
                    float bx = sb1[cc], by = sb1[cc + 1];
                    float h0 = fmaxf(a4[0] + bx, 0.f), h1 = fmaxf(a4[1] + by, 0.f);
                    float h2 = fmaxf(a4[2] + bx, 0.f), h3 = fmaxf(a4[3] + by, 0.f);
                    __half2 hiA = __floats2half2_rn(h0, h1);
                    __half2 hiB = __floats2half2_rn(h2, h3);
                    *(__half2*)(smem + OFF_AHI + r * AS + cc * 2)       = hiA;
                    *(__half2*)(smem + OFF_AHI + (r + 8) * AS + cc * 2) = hiB;
                }
            __syncthreads();   // h visible to all warps before GEMM2
            #pragma unroll
            for (int i = 0; i < 2; ++i)
                #pragma unroll
                for (int j = 0; j < 4; ++j)
                    #pragma unroll
                    for (int q = 0; q < 4; ++q) acc[i][j][q] = 0.f;
        }
    }

    // ---- final epilogue: g = h * sigmoid(D2+b2); g overlays A region ----
    float* gt = (float*)smem;   // [32][264] fp32 over A region
    {
        float gv[2][4][4];
        #pragma unroll
        for (int mt = 0; mt < 2; ++mt)
            #pragma unroll
            for (int j = 0; j < 4; ++j) {
                float* a4 = acc[mt][j];
                int r  = mt * 16 + (lane >> 2);
                int cc = w * 32 + j * 8 + (lane & 3) * 2;
                float bx = sb2[cc], by = sb2[cc + 1];
                float2 hA = __half22float2(*(__half2*)(smem + OFF_AHI + r * AS + cc * 2));
                float2 hB = __half22float2(*(__half2*)(smem + OFF_AHI + (r + 8) * AS + cc * 2));
                gv[mt][j][0] = hA.x / (1.f + __expf(-(a4[0] + bx)));
                gv[mt][j][1] = hA.y / (1.f + __expf(-(a4[1] + by)));
                gv[mt][j][2] = hB.x / (1.f + __expf(-(a4[2] + bx)));
                gv[mt][j][3] = hB.y / (1.f + __expf(-(a4[3] + by)));
            }
        __syncthreads();   // everyone done reading h before overwrite
        #pragma unroll
        for (int mt = 0; mt < 2; ++mt)
            #pragma unroll
            for (int j = 0; j < 4; ++j) {
                int r  = mt * 16 + (lane >> 2);
                int cc = w * 32 + j * 8 + (lane & 3) * 2;
                *(float2*)&gt[r * 264 + cc]       = make_float2(gv[mt][j][0], gv[mt][j][1]);
                *(float2*)&gt[(r + 8) * 264 + cc] = make_float2(gv[mt][j][2], gv[mt][j][3]);
            }
    }
    __syncthreads();

    // ---- segment reduction: sorted batch -> runs; one thread per column ----
    {
        const int ccol = tid;              // 256 threads = 256 columns
        int cur = bseg[0];
        float rsum = 0.f, rmax = 0.f;
        #pragma unroll 1
        for (int r = 0; r < BM; ++r) {
            int s = bseg[r];
            float g = gt[r * 264 + ccol];
            if (s != cur) {
                if (cur >= 0) {
                    atomicAdd(&out[(size_t)cur * 2 * H + H + ccol], rsum);
                    atomicMax((unsigned int*)&out[(size_t)cur * 2 * H + ccol],
                              __float_as_uint(rmax));   // g >= 0 always
                }
                cur = s; rsum = 0.f; rmax = 0.f;
            }
            if (s >= 0) { rsum += g; rmax = fmaxf(rmax, g); }
        }
        if (cur >= 0) {
            atomicAdd(&out[(size_t)cur * 2 * H + H + ccol], rsum);
            atomicMax((unsigned int*)&out[(size_t)cur * 2 * H + ccol],
                      __float_as_uint(rmax));
        }
    }
}

// ---------------------------------------------------------------------------
// Kernel 3: mean = sum / count (count via binary search on sorted batch).
// ---------------------------------------------------------------------------
__global__ void finalize_kernel(float* out, const void* batch, int N) {
    __shared__ float inv;
    int seg = blockIdx.x;
    if (threadIdx.x == 0) {
        int lb, ub;
        if (g_is64) {
            const long long* b = (const long long*)batch;
            int lo = 0, hi = N;
            while (lo < hi) { int m = (lo + hi) >> 1; if (b[m] < (long long)seg) lo = m + 1; else hi = m; }
            lb = lo;
            lo = lb; hi = N;
            while (lo < hi) { int m = (lo + hi) >> 1; if (b[m] < (long long)(seg + 1)) lo = m + 1; else hi = m; }
            ub = lo;
        } else {
            const int* b = (const int*)batch;
            int lo = 0, hi = N;
            while (lo < hi) { int m = (lo + hi) >> 1; if (b[m] < seg) lo = m + 1; else hi = m; }
            lb = lo;
            lo = lb; hi = N;
            while (lo < hi) { int m = (lo + hi) >> 1; if (b[m] < seg + 1) lo = m + 1; else hi = m; }
            ub = lo;
        }
        int cnt = ub - lb;
        inv = cnt > 0 ? 1.0f / (float)cnt : 1.0f;
    }
    __syncthreads();
    out[(size_t)seg * 2 * H + H + threadIdx.x] *= inv;
}

extern "C" void kernel_launch(void* const* d_in, const int* in_sizes, int n_in,
                              void* d_out, int out_size) {
    const float* x     = (const float*)d_in[0];
    const void*  batch = d_in[1];
    const float* W1    = (const float*)d_in[2];
    const float* b1    = (const float*)d_in[3];
    const float* W2    = (const float*)d_in[4];
    const float* b2    = (const float*)d_in[5];
    float* out = (float*)d_out;

    int N = in_sizes[0] / H;

    cudaFuncSetAttribute(fused_kernel,
                         cudaFuncAttributeMaxDynamicSharedMemorySize, SMEM_TOTAL);

    prep_kernel<<<512, 256>>>(W1, W2, out, batch, N);

    int nblk = (N + BM - 1) / BM;
    fused_kernel<<<nblk, 256, SMEM_TOTAL>>>(x, batch, b1, b2, out, N);

    finalize_kernel<<<NSEG, 256>>>(out, batch, N);
}

// round 16
// speedup vs baseline: 1.6951x; 1.1335x over previous
#include <cuda_runtime.h>
#include <cuda_fp16.h>
#include <cstdint>
#include <math.h>

#define H 256
#define BM 32
#define NSEG 512
#define AS 528           // A row stride in bytes (264 fp16, padded)

typedef unsigned long long u64;
typedef unsigned int       u32;

// -------- device scratch (no allocations allowed) --------
__device__ int g_is64;
// W (fp16) packed in per-lane b-fragment layout (coalesced LDG.64):
// u32 offset = gemm*32768 + kstep*2048 + nt*64 + lane*2 + reg
__device__ __align__(16) u32 g_Wb[65536];

// -------- SMEM layout (bytes) --------
#define OFF_AHI   0                    // [32][264] fp16 = 16896
// g tile (final): fp32 [32][264] = 33792 bytes overlays 0..33791
#define OFF_BSEG  33792                // 32 ints = 128
#define OFF_BIAS  33920                // b1[256], b2[256] fp32 = 2048
#define SMEM_TOTAL 35968

// -------- PTX helpers (legal on plain sm_103 target) --------
__device__ __forceinline__ void ldm4(u32* r, u32 addr) {
    asm volatile("ldmatrix.sync.aligned.m8n8.x4.shared.b16 {%0,%1,%2,%3},[%4];"
        : "=r"(r[0]), "=r"(r[1]), "=r"(r[2]), "=r"(r[3]) : "r"(addr));
}
__device__ __forceinline__ void mma16816(float* d, const u32* a, const u32* b) {
    asm volatile(
        "mma.sync.aligned.m16n8k16.row.col.f32.f16.f16.f32 "
        "{%0,%1,%2,%3},{%4,%5,%6,%7},{%8,%9},{%0,%1,%2,%3};"
        : "+f"(d[0]), "+f"(d[1]), "+f"(d[2]), "+f"(d[3])
        : "r"(a[0]), "r"(a[1]), "r"(a[2]), "r"(a[3]), "r"(b[0]), "r"(b[1]));
}

// ---------------------------------------------------------------------------
// Kernel 1: W prep (fp32 -> fp16, b-fragment layout) + zero out + batch
// dtype detection. 512 blocks x 256 threads.
// ---------------------------------------------------------------------------
__global__ void prep_kernel(const float* __restrict__ W1,
                            const float* __restrict__ W2,
                            float* out,
                            const void* batch, int N) {
    int id = blockIdx.x * 256 + threadIdx.x;     // 131072 total
    // zero output (262144 floats)
    out[id] = 0.0f;
    out[id + 131072] = 0.0f;
    if (id == 0) {
        const int* bw = (const int*)batch;
        int o = ((N - 1) & 1) ? (N - 1) : (N - 2);
        int orv = 0;
        if (o >= 4) orv = bw[o] | bw[o - 2] | bw[o - 4];
        else if (o >= 0) orv = bw[o];
        g_is64 = (orv == 0) ? 1 : 0;
    }
    // W pack: offset(gemm, kstep=k>>4) = gemm*32768 + kstep*2048 (+ frag)
    int gemm = id >> 16, rem = id & 65535;
    int n = rem >> 8, k = rem & 255;
    float w = (gemm ? W2 : W1)[n * H + k];
    __half hi = __float2half_rn(w);
    int kstep = k >> 4, kk = k & 15;
    int nt = n >> 3, nn = n & 7;
    int lane = nn * 4 + ((kk & 7) >> 1);
    int reg  = kk >> 3;
    int half_i = kk & 1;
    u32 base = (u32)(gemm * 32768 + kstep * 2048 + (nt * 32 + lane) * 2 + reg);
    __half* wb = (__half*)g_Wb;
    wb[(size_t)base * 2 + half_i] = hi;
}

// ---------------------------------------------------------------------------
// Kernel 2: fused  relu(xW1^T+b1) -> sigmoid(hW2^T+b2) gate -> segment reduce.
// Plain fp16 HMMA. BM=32 tile, warp grid 1x8 (mt=2, nt=4), no B duplication.
// 4 CTAs/SM (8 warps/SMSP) — occupancy is the measured dominant lever.
// Addressing reduced to pointer increments to fit the 64-reg budget.
// ---------------------------------------------------------------------------
extern "C" __global__ void __launch_bounds__(256, 4)
fused_kernel(const float* __restrict__ x, const void* __restrict__ batch,
             const float* __restrict__ b1, const float* __restrict__ b2,
             float* __restrict__ out, int N)
{
    extern __shared__ char smem[];
    const u32 sb = (u32)__cvta_generic_to_shared(smem);
    const int tid  = threadIdx.x;
    const int w    = tid >> 5;          // warp 0..7: output cols w*32..w*32+31
    const int lane = tid & 31;
    const int row0 = blockIdx.x * BM;
    float* sb1 = (float*)(smem + OFF_BIAS);
    float* sb2 = sb1 + H;
    int* bseg = (int*)(smem + OFF_BSEG);

    // ---- bias + segment ids ----
    sb1[tid] = b1[tid];
    sb2[tid] = b2[tid];
    if (tid < BM) {
        int r = row0 + tid;
        int s = -1;
        if (r < N) {
            if (g_is64) s = (int)((const long long*)batch)[r];
            else        s = ((const int*)batch)[r];
        }
        bseg[tid] = s;
    }

    // ---- load x tile fp32 -> fp16 into AHI ([32][264] padded) ----
    {
        const float4* xg = (const float4*)x;
        #pragma unroll
        for (int it = 0; it < 8; ++it) {
            int f = tid + it * 256;            // 2048 float4s
            int r = f >> 6, k4 = f & 63;
            float4 v = make_float4(0.f, 0.f, 0.f, 0.f);
            if (row0 + r < N) v = xg[(size_t)(row0 + r) * (H / 4) + k4];
            __half2 h01 = __floats2half2_rn(v.x, v.y);
            __half2 h23 = __floats2half2_rn(v.z, v.w);
            char* pa = smem + OFF_AHI + r * AS + k4 * 8;
            *(__half2*)pa = h01;  *(__half2*)(pa + 4) = h23;
        }
    }
    __syncthreads();   // x tile visible to all warps

    float acc[2][4][4];
    #pragma unroll
    for (int i = 0; i < 2; ++i)
        #pragma unroll
        for (int j = 0; j < 4; ++j)
            #pragma unroll
            for (int q = 0; q < 4; ++q) acc[i][j][q] = 0.f;

    // ---- 2 GEMMs, K=256 = 16 full k16-steps each ----
    #pragma unroll 1
    for (int g = 0; g < 2; ++g) {
        // per-warp base pointer into packed W; advances 2048 u32 per k-step
        const u32* bp = g_Wb + g * 32768 + (u32)(w * 256 + lane * 2);

        uint2 bh[2][4];
        #pragma unroll
        for (int j = 0; j < 4; ++j)
            bh[0][j] = __ldg((const uint2*)(bp + j * 64));

        // A smem address; advances 32 bytes per k-step
        u32 ap = sb + OFF_AHI + (lane & 15) * AS + ((lane >> 4) << 4);

        u32 ah[2][4];
        #pragma unroll 2
        for (int ks = 0; ks < 16; ++ks) {
            const int cur = ks & 1;
            ldm4(ah[0], ap);
            ldm4(ah[1], ap + 16 * AS);
            ap += 32;
            // prefetch next full step's B fragments
            if (ks < 15) {
                const u32* pn = bp + 2048;
                #pragma unroll
                for (int j = 0; j < 4; ++j)
                    bh[cur ^ 1][j] = __ldg((const uint2*)(pn + j * 64));
            }
            bp += 2048;
            // 8 MMAs: 2 mt x 4 nt
            #pragma unroll
            for (int mt = 0; mt < 2; ++mt)
                #pragma unroll
                for (int j = 0; j < 4; ++j)
                    mma16816(acc[mt][j], ah[mt], (const u32*)&bh[cur][j]);
        }

        // ---- GEMM boundary: h = relu(D1+b1) -> fp16 back into A ----
        if (g == 0) {
            __syncthreads();   // all warps done READING x before overwrite
            #pragma unroll
            for (int mt = 0; mt < 2; ++mt)
                #pragma unroll
                for (int j = 0; j < 4; ++j) {
                    float* a4 = acc[mt][j];
                    int r  = mt * 16 + (lane >> 2);
                    int cc = w * 32 + j * 8 + (lane & 3) * 2;
                    float bx = sb1[cc], by = sb1[cc + 1];
                    float h0 = fmaxf(a4[0] + bx, 0.f), h1 = fmaxf(a4[1] + by, 0.f);
                    float h2 = fmaxf(a4[2] + bx, 0.f), h3 = fmaxf(a4[3] + by, 0.f);
                    __half2 hiA = __floats2half2_rn(h0, h1);
                    __half2 hiB = __floats2half2_rn(h2, h3);
                    *(__half2*)(smem + OFF_AHI + r * AS + cc * 2)       = hiA;
                    *(__half2*)(smem + OFF_AHI + (r + 8) * AS + cc * 2) = hiB;
                }
            __syncthreads();   // h visible to all warps before GEMM2
            #pragma unroll
            for (int i = 0; i < 2; ++i)
                #pragma unroll
                for (int j = 0; j < 4; ++j)
                    #pragma unroll
                    for (int q = 0; q < 4; ++q) acc[i][j][q] = 0.f;
        }
    }

    // ---- final epilogue: g = h * sigmoid(D2+b2); g overlays A region ----
    float* gt = (float*)smem;   // [32][264] fp32 over A region
    {
        float gv[2][4][4];
        #pragma unroll
        for (int mt = 0; mt < 2; ++mt)
            #pragma unroll
            for (int j = 0; j < 4; ++j) {
                float* a4 = acc[mt][j];
                int r  = mt * 16 + (lane >> 2);
                int cc = w * 32 + j * 8 + (lane & 3) * 2;
                float bx = sb2[cc], by = sb2[cc + 1];
                float2 hA = __half22float2(*(__half2*)(smem + OFF_AHI + r * AS + cc * 2));
                float2 hB = __half22float2(*(__half2*)(smem + OFF_AHI + (r + 8) * AS + cc * 2));
                gv[mt][j][0] = hA.x / (1.f + __expf(-(a4[0] + bx)));
                gv[mt][j][1] = hA.y / (1.f + __expf(-(a4[1] + by)));
                gv[mt][j][2] = hB.x / (1.f + __expf(-(a4[2] + bx)));
                gv[mt][j][3] = hB.y / (1.f + __expf(-(a4[3] + by)));
            }
        __syncthreads();   // everyone done reading h before overwrite
        #pragma unroll
        for (int mt = 0; mt < 2; ++mt)
            #pragma unroll
            for (int j = 0; j < 4; ++j) {
                int r  = mt * 16 + (lane >> 2);
                int cc = w * 32 + j * 8 + (lane & 3) * 2;
                *(float2*)&gt[r * 264 + cc]       = make_float2(gv[mt][j][0], gv[mt][j][1]);
                *(float2*)&gt[(r + 8) * 264 + cc] = make_float2(gv[mt][j][2], gv[mt][j][3]);
            }
    }
    __syncthreads();

    // ---- segment reduction: sorted batch -> runs; one thread per column ----
    {
        const int ccol = tid;              // 256 threads = 256 columns
        int cur = bseg[0];
        float rsum = 0.f, rmax = 0.f;
        #pragma unroll 1
        for (int r = 0; r < BM; ++r) {
            int s = bseg[r];
            float g = gt[r * 264 + ccol];
            if (s != cur) {
                if (cur >= 0) {
                    atomicAdd(&out[(size_t)cur * 2 * H + H + ccol], rsum);
                    atomicMax((unsigned int*)&out[(size_t)cur * 2 * H + ccol],
                              __float_as_uint(rmax));   // g >= 0 always
                }
                cur = s; rsum = 0.f; rmax = 0.f;
            }
            if (s >= 0) { rsum += g; rmax = fmaxf(rmax, g); }
        }
        if (cur >= 0) {
            atomicAdd(&out[(size_t)cur * 2 * H + H + ccol], rsum);
            atomicMax((unsigned int*)&out[(size_t)cur * 2 * H + ccol],
                      __float_as_uint(rmax));
        }
    }
}

// ---------------------------------------------------------------------------
// Kernel 3: mean = sum / count (count via binary search on sorted batch).
// ---------------------------------------------------------------------------
__global__ void finalize_kernel(float* out, const void* batch, int N) {
    __shared__ float inv;
    int seg = blockIdx.x;
    if (threadIdx.x == 0) {
        int lb, ub;
        if (g_is64) {
            const long long* b = (const long long*)batch;
            int lo = 0, hi = N;
            while (lo < hi) { int m = (lo + hi) >> 1; if (b[m] < (long long)seg) lo = m + 1; else hi = m; }
            lb = lo;
            lo = lb; hi = N;
            while (lo < hi) { int m = (lo + hi) >> 1; if (b[m] < (long long)(seg + 1)) lo = m + 1; else hi = m; }
            ub = lo;
        } else {
            const int* b = (const int*)batch;
            int lo = 0, hi = N;
            while (lo < hi) { int m = (lo + hi) >> 1; if (b[m] < seg) lo = m + 1; else hi = m; }
            lb = lo;
            lo = lb; hi = N;
            while (lo < hi) { int m = (lo + hi) >> 1; if (b[m] < seg + 1) lo = m + 1; else hi = m; }
            ub = lo;
        }
        int cnt = ub - lb;
        inv = cnt > 0 ? 1.0f / (float)cnt : 1.0f;
    }
    __syncthreads();
    out[(size_t)seg * 2 * H + H + threadIdx.x] *= inv;
}

extern "C" void kernel_launch(void* const* d_in, const int* in_sizes, int n_in,
                              void* d_out, int out_size) {
    const float* x     = (const float*)d_in[0];
    const void*  batch = d_in[1];
    const float* W1    = (const float*)d_in[2];
    const float* b1    = (const float*)d_in[3];
    const float* W2    = (const float*)d_in[4];
    const float* b2    = (const float*)d_in[5];
    float* out = (float*)d_out;

    int N = in_sizes[0] / H;

    cudaFuncSetAttribute(fused_kernel,
                         cudaFuncAttributeMaxDynamicSharedMemorySize, SMEM_TOTAL);

    prep_kernel<<<512, 256>>>(W1, W2, out, batch, N);

    int nblk = (N + BM - 1) / BM;
    fused_kernel<<<nblk, 256, SMEM_TOTAL>>>(x, batch, b1, b2, out, N);

    finalize_kernel<<<NSEG, 256>>>(out, batch, N);
}